// round 12
// baseline (speedup 1.0000x reference)
#include <cuda_runtime.h>
#include <cuda_bf16.h>
#include <cstdint>

typedef __nv_bfloat16 bf16;

#define T_SEQ 4096
#define C_DIM 768
#define H_NUM 12
#define D_DIM 64
#define NQKV  2304

// ---------------- scratch (__device__ globals; no allocation) ----------------
__device__ bf16 g_xhi[T_SEQ * C_DIM], g_xlo[T_SEQ * C_DIM];
__device__ bf16 g_wqhi[NQKV * C_DIM], g_wqlo[NQKV * C_DIM];      // W_qkv^T [N][K]
__device__ bf16 g_wphi[C_DIM * C_DIM], g_wplo[C_DIM * C_DIM];    // W_proj^T [N][K]
__device__ bf16 g_qhi[H_NUM * T_SEQ * D_DIM], g_qlo[H_NUM * T_SEQ * D_DIM];   // [h][t][d], q/8
__device__ bf16 g_khi[H_NUM * T_SEQ * D_DIM], g_klo[H_NUM * T_SEQ * D_DIM];   // [h][t][d]
__device__ bf16 g_vthi[H_NUM * D_DIM * T_SEQ], g_vtlo[H_NUM * D_DIM * T_SEQ]; // [h][d][t]
__device__ bf16 g_yhi[T_SEQ * C_DIM], g_ylo[T_SEQ * C_DIM];

// ---------------- helpers ----------------
__device__ __forceinline__ uint32_t sw128(uint32_t o) { return o ^ ((o >> 3) & 0x70); }
__device__ __forceinline__ uint32_t sw32(uint32_t o) { return o ^ ((o >> 3) & 0x10); }
__device__ __forceinline__ uint32_t smem_u32(const void* p) {
    uint32_t a;
    asm("{ .reg .u64 t; cvta.to.shared.u64 t, %1; cvt.u32.u64 %0, t; }" : "=r"(a) : "l"(p));
    return a;
}
__device__ __forceinline__ void cp16(uint32_t dst, const void* src) {
    asm volatile("cp.async.cg.shared.global [%0], [%1], 16;" :: "r"(dst), "l"(src));
}
__device__ __forceinline__ void cp_commit() { asm volatile("cp.async.commit_group;"); }
template <int N>
__device__ __forceinline__ void cp_wait() {
    asm volatile("cp.async.wait_group %0;" :: "n"(N));
}
__device__ __forceinline__ void ldm4(uint32_t r[4], uint32_t addr) {
    asm volatile("ldmatrix.sync.aligned.m8n8.x4.shared.b16 {%0,%1,%2,%3}, [%4];"
                 : "=r"(r[0]), "=r"(r[1]), "=r"(r[2]), "=r"(r[3]) : "r"(addr));
}
__device__ __forceinline__ void mma16816(float* c, const uint32_t a[4], uint32_t b0,
                                         uint32_t b1) {
    asm volatile("mma.sync.aligned.m16n8k16.row.col.f32.bf16.bf16.f32 "
                 "{%0,%1,%2,%3}, {%4,%5,%6,%7}, {%8,%9}, {%0,%1,%2,%3};"
                 : "+f"(c[0]), "+f"(c[1]), "+f"(c[2]), "+f"(c[3])
                 : "r"(a[0]), "r"(a[1]), "r"(a[2]), "r"(a[3]), "r"(b0), "r"(b1));
}
__device__ __forceinline__ void split2(float v, bf16& h, bf16& l) {
    h = __float2bfloat16(v);
    l = __float2bfloat16(v - __bfloat162float(h));
}
__device__ __forceinline__ uint32_t pack2bf(bf16 a, bf16 b) {
    return (uint32_t)__bfloat16_as_ushort(a) | ((uint32_t)__bfloat16_as_ushort(b) << 16);
}
__device__ __forceinline__ void store_split_pair(bf16* hiA, bf16* loA, size_t idx, float v0,
                                                 float v1) {
    bf16 h0, l0, h1, l1;
    split2(v0, h0, l0);
    split2(v1, h1, l1);
    *(uint32_t*)(hiA + idx) = pack2bf(h0, h1);
    *(uint32_t*)(loA + idx) = pack2bf(l0, l1);
}

// ldmatrix x4 address in a [rows][64 halves] tile, 128B rows, SW128
__device__ __forceinline__ uint32_t mat_addr128(uint32_t base, int rbase, int kbase, int lane) {
    int row = rbase + (lane & 15);
    uint32_t off = row * 128 + kbase * 2 + ((lane >> 4) << 4);
    return base + sw128(off);
}
// ldmatrix x4 address in a [rows][16 halves] tile, 32B rows, sw32
__device__ __forceinline__ uint32_t mat_addr32(uint32_t base, int rbase, int lane) {
    int row = rbase + (lane & 15);
    uint32_t off = row * 32 + ((lane >> 4) << 4);
    return base + sw32(off);
}

// async tile loads
template <int ROWS, int NT>
__device__ __forceinline__ void load_tile128(uint32_t dst, const bf16* __restrict__ src,
                                             int ldK, int tid) {
#pragma unroll
    for (int i = 0; i < ROWS * 8 / NT; i++) {
        int ch = tid + i * NT;
        int row = ch >> 3, ci = ch & 7;
        cp16(dst + sw128(row * 128 + ci * 16), src + (size_t)row * ldK + ci * 8);
    }
}
template <int ROWS, int NT>
__device__ __forceinline__ void load_tile32(uint32_t dst, const bf16* __restrict__ src,
                                            int ldK, int tid) {
#pragma unroll
    for (int i = 0; i < ROWS * 2 / NT; i++) {
        int ch = tid + i * NT;
        int row = ch >> 1, ci = ch & 1;
        cp16(dst + sw32(row * 32 + ci * 16), src + (size_t)row * ldK + ci * 8);
    }
}

// ---------------- converters ----------------
__global__ void conv_x_kernel(const float* __restrict__ x) {
    int i = (blockIdx.x * blockDim.x + threadIdx.x) * 4;
    float4 v = *(const float4*)(x + i);
    float e[4] = {v.x, v.y, v.z, v.w};
#pragma unroll
    for (int j = 0; j < 4; j++) {
        bf16 h, l;
        split2(e[j], h, l);
        g_xhi[i + j] = h;
        g_xlo[i + j] = l;
    }
}
__global__ void transpose_split(const float* __restrict__ W, bf16* __restrict__ hi,
                                bf16* __restrict__ lo, int K, int N) {
    __shared__ float t[32][33];
    int n0 = blockIdx.x * 32, k0 = blockIdx.y * 32;
    int tx = threadIdx.x, ty = threadIdx.y;
#pragma unroll
    for (int i = 0; i < 4; i++) t[ty + i * 8][tx] = W[(size_t)(k0 + ty + i * 8) * N + n0 + tx];
    __syncthreads();
#pragma unroll
    for (int i = 0; i < 4; i++) {
        int n = n0 + ty + i * 8;
        bf16 h, l;
        split2(t[tx][ty + i * 8], h, l);
        hi[(size_t)n * K + k0 + tx] = h;
        lo[(size_t)n * K + k0 + tx] = l;
    }
}

// ---------------- HMMA GEMM: D[128x128] = A[128xK] . B^T, B stored [N][K] ----------
// 3-stage cp.async ring, ONE barrier per stage: wait -> sync -> issue(s+2) -> compute(s).
template <int MODE>
__global__ __launch_bounds__(256) void mma_gemm(const bf16* __restrict__ Ahi,
                                                const bf16* __restrict__ Alo,
                                                const bf16* __restrict__ Bhi,
                                                const bf16* __restrict__ Blo,
                                                const float* __restrict__ bias,
                                                float* __restrict__ Cout, int N, int K) {
    __shared__ char smem[49152];
    uint32_t sb = smem_u32(smem);
    const int tid = threadIdx.x, lane = tid & 31, warp = tid >> 5;
    const int wm = warp >> 2, wn = warp & 3;  // 2 x 4 warp grid, 64m x 32n per warp
    const int m0 = blockIdx.y * 128, n0 = blockIdx.x * 128;

    const bf16* Ah = Ahi + (size_t)m0 * K;
    const bf16* Al = Alo + (size_t)m0 * K;
    const bf16* Bh = Bhi + (size_t)n0 * K;
    const bf16* Bl = Blo + (size_t)n0 * K;

    float acc[4][4][4];
#pragma unroll
    for (int mt = 0; mt < 4; mt++)
#pragma unroll
        for (int nt = 0; nt < 4; nt++)
#pragma unroll
            for (int e = 0; e < 4; e++) acc[mt][nt][e] = 0.0f;

    const int NS = K / 16;
    // prefetch stages 0,1
#pragma unroll
    for (int p = 0; p < 2; p++) {
        uint32_t b = sb + p * 16384;
        int k0 = p * 16;
        load_tile32<128, 256>(b, Ah + k0, K, tid);
        load_tile32<128, 256>(b + 4096, Al + k0, K, tid);
        load_tile32<128, 256>(b + 8192, Bh + k0, K, tid);
        load_tile32<128, 256>(b + 12288, Bl + k0, K, tid);
        cp_commit();
    }
#pragma unroll 1
    for (int s = 0; s < NS; s++) {
        if (s + 1 < NS) cp_wait<1>();
        else cp_wait<0>();
        __syncthreads();  // stage s readable; all threads past stage s-1 compute
        if (s + 2 < NS) {  // safe: buffer (s+2)%3 == (s-1)%3, reads finished above
            uint32_t b = sb + ((s + 2) % 3) * 16384;
            int k0 = (s + 2) * 16;
            load_tile32<128, 256>(b, Ah + k0, K, tid);
            load_tile32<128, 256>(b + 4096, Al + k0, K, tid);
            load_tile32<128, 256>(b + 8192, Bh + k0, K, tid);
            load_tile32<128, 256>(b + 12288, Bl + k0, K, tid);
            cp_commit();
        }
        uint32_t b = sb + (s % 3) * 16384;
        uint32_t ah[4][4], al[4][4];
#pragma unroll
        for (int mt = 0; mt < 4; mt++) {
            ldm4(ah[mt], mat_addr32(b, wm * 64 + mt * 16, lane));
            ldm4(al[mt], mat_addr32(b + 4096, wm * 64 + mt * 16, lane));
        }
#pragma unroll
        for (int p = 0; p < 2; p++) {
            uint32_t bh[4], bl[4];
            ldm4(bh, mat_addr32(b + 8192, wn * 32 + p * 16, lane));
            ldm4(bl, mat_addr32(b + 12288, wn * 32 + p * 16, lane));
#pragma unroll
            for (int mt = 0; mt < 4; mt++)
#pragma unroll
                for (int q = 0; q < 2; q++) {
                    int nt = p * 2 + q;
                    mma16816(acc[mt][nt], ah[mt], bh[q], bh[2 + q]);
                    mma16816(acc[mt][nt], ah[mt], bl[q], bl[2 + q]);
                    mma16816(acc[mt][nt], al[mt], bh[q], bh[2 + q]);
                }
        }
    }

    // epilogue: acc[mt][nt]: rows r0,r0+8 ; cols c0,c0+1
#pragma unroll
    for (int mt = 0; mt < 4; mt++)
#pragma unroll
        for (int nt = 0; nt < 4; nt++) {
            int r0 = m0 + wm * 64 + mt * 16 + (lane >> 2);
            int c0 = n0 + wn * 32 + nt * 8 + 2 * (lane & 3);
            float bv0 = bias[c0], bv1 = bias[c0 + 1];
            float v0 = acc[mt][nt][0] + bv0, v1 = acc[mt][nt][1] + bv1;
            float v2 = acc[mt][nt][2] + bv0, v3 = acc[mt][nt][3] + bv1;
            if (MODE == 1) {
                float2 p0 = make_float2(v0, v1), p1 = make_float2(v2, v3);
                *(float2*)&Cout[(size_t)r0 * N + c0] = p0;
                *(float2*)&Cout[(size_t)(r0 + 8) * N + c0] = p1;
            } else {
                int which = n0 / C_DIM;
                int cm = c0 % C_DIM;
                int h = cm >> 6, d = cm & 63;
                if (which == 0) {
                    store_split_pair(g_qhi, g_qlo, ((size_t)h * T_SEQ + r0) * D_DIM + d,
                                     v0 * 0.125f, v1 * 0.125f);
                    store_split_pair(g_qhi, g_qlo, ((size_t)h * T_SEQ + r0 + 8) * D_DIM + d,
                                     v2 * 0.125f, v3 * 0.125f);
                } else if (which == 1) {
                    store_split_pair(g_khi, g_klo, ((size_t)h * T_SEQ + r0) * D_DIM + d, v0, v1);
                    store_split_pair(g_khi, g_klo, ((size_t)h * T_SEQ + r0 + 8) * D_DIM + d, v2,
                                     v3);
                } else {
                    size_t b0 = ((size_t)h * D_DIM + d) * T_SEQ;
                    size_t b1 = ((size_t)h * D_DIM + d + 1) * T_SEQ;
                    bf16 hh, ll;
                    split2(v0, hh, ll); g_vthi[b0 + r0] = hh; g_vtlo[b0 + r0] = ll;
                    split2(v1, hh, ll); g_vthi[b1 + r0] = hh; g_vtlo[b1 + r0] = ll;
                    split2(v2, hh, ll); g_vthi[b0 + r0 + 8] = hh; g_vtlo[b0 + r0 + 8] = ll;
                    split2(v3, hh, ll); g_vthi[b1 + r0 + 8] = hh; g_vtlo[b1 + r0 + 8] = ll;
                }
            }
        }
}

// ---------------- flash attention on HMMA: 128-row q-tiles, 8 warps ----------------
// grid (32, 12); qb = 31 - bx (longest blocks first, LPT). Warp w owns rows w*16..+15.
// smem: Khi 8K | Klo 8K | Vhi 8K | Vlo 8K (full 32KB doubles as 128-row Q staging).
// Staggered prefetch: K_j waited at iter top (V_j in flight behind S); K_{j+1} issued
// before softmax/PV; V_{j+1} issued after the V-read barrier.
__global__ __launch_bounds__(256, 1) void flash_mma() {
    __shared__ char smem[32768];
    uint32_t sb = smem_u32(smem);
    const int tid = threadIdx.x, lane = tid & 31, w = tid >> 5;
    const int h = blockIdx.y;
    const int qb = 31 - (int)blockIdx.x;
    const int qm0 = qb * 128;
    const int r0l = lane >> 2;
    const int c0l = 2 * (lane & 3);

    const bf16* khB = g_khi + (size_t)h * T_SEQ * D_DIM;
    const bf16* klB = g_klo + (size_t)h * T_SEQ * D_DIM;
    const bf16* vhB = g_vthi + (size_t)h * D_DIM * T_SEQ;
    const bf16* vlB = g_vtlo + (size_t)h * D_DIM * T_SEQ;

    // Q staging: 128 rows hi at sb, lo at sb+16K
    load_tile128<128, 256>(sb, g_qhi + ((size_t)h * T_SEQ + qm0) * D_DIM, D_DIM, tid);
    load_tile128<128, 256>(sb + 16384, g_qlo + ((size_t)h * T_SEQ + qm0) * D_DIM, D_DIM, tid);
    cp_commit();
    cp_wait<0>();
    __syncthreads();

    uint32_t qh[4][4], ql[4][4];
#pragma unroll
    for (int kt = 0; kt < 4; kt++) {
        ldm4(qh[kt], mat_addr128(sb, w * 16, kt * 16, lane));
        ldm4(ql[kt], mat_addr128(sb + 16384, w * 16, kt * 16, lane));
    }
    __syncthreads();  // all warps done reading Q staging before K0/V0 overwrite

    // issue K0 then V0 as separate groups
    load_tile128<64, 256>(sb, khB, D_DIM, tid);
    load_tile128<64, 256>(sb + 8192, klB, D_DIM, tid);
    cp_commit();
    load_tile128<64, 256>(sb + 16384, vhB, T_SEQ, tid);
    load_tile128<64, 256>(sb + 24576, vlB, T_SEQ, tid);
    cp_commit();

    float mi0 = -1e30f, mi1 = -1e30f, li0 = 0.0f, li1 = 0.0f;
    float O[8][4];
#pragma unroll
    for (int nt = 0; nt < 8; nt++)
#pragma unroll
        for (int e = 0; e < 4; e++) O[nt][e] = 0.0f;

    const int nkv = 2 * qb + 2;
#pragma unroll 1
    for (int j = 0; j < nkv; j++) {
        const int kv0 = j * 64;
        cp_wait<1>();  // K_j complete (V_j may still be in flight)
        __syncthreads();

        // S = Q . K^T
        float S[8][4];
#pragma unroll
        for (int nt = 0; nt < 8; nt++)
#pragma unroll
            for (int e = 0; e < 4; e++) S[nt][e] = 0.0f;
#pragma unroll
        for (int p = 0; p < 4; p++)
#pragma unroll
            for (int kt = 0; kt < 4; kt++) {
                uint32_t kh[4], kl[4];
                ldm4(kh, mat_addr128(sb, p * 16, kt * 16, lane));
                ldm4(kl, mat_addr128(sb + 8192, p * 16, kt * 16, lane));
#pragma unroll
                for (int q = 0; q < 2; q++) {
                    int nt = 2 * p + q;
                    mma16816(S[nt], qh[kt], kh[q], kh[2 + q]);
                    mma16816(S[nt], qh[kt], kl[q], kl[2 + q]);
                    mma16816(S[nt], ql[kt], kh[q], kh[2 + q]);
                }
            }

        cp_wait<0>();     // V_j complete
        __syncthreads();  // all warps done reading K_j

        // prefetch K_{j+1} over softmax + PV compute
        if (j + 1 < nkv) {
            load_tile128<64, 256>(sb, khB + (size_t)(kv0 + 64) * D_DIM, D_DIM, tid);
            load_tile128<64, 256>(sb + 8192, klB + (size_t)(kv0 + 64) * D_DIM, D_DIM, tid);
            cp_commit();
        }

        if (j >= 2 * qb) {  // diagonal tiles: causal mask
            int rg0 = qm0 + w * 16 + r0l, rg1 = rg0 + 8;
#pragma unroll
            for (int nt = 0; nt < 8; nt++) {
                int cg = kv0 + nt * 8 + c0l;
                if (cg > rg0) S[nt][0] = -1e30f;
                if (cg + 1 > rg0) S[nt][1] = -1e30f;
                if (cg > rg1) S[nt][2] = -1e30f;
                if (cg + 1 > rg1) S[nt][3] = -1e30f;
            }
        }

        // online softmax (rows r0l, r0l+8; reduce over lanes xor 1,2)
        float rm0 = -1e30f, rm1 = -1e30f;
#pragma unroll
        for (int nt = 0; nt < 8; nt++) {
            rm0 = fmaxf(rm0, fmaxf(S[nt][0], S[nt][1]));
            rm1 = fmaxf(rm1, fmaxf(S[nt][2], S[nt][3]));
        }
        rm0 = fmaxf(rm0, __shfl_xor_sync(0xffffffffu, rm0, 1));
        rm0 = fmaxf(rm0, __shfl_xor_sync(0xffffffffu, rm0, 2));
        rm1 = fmaxf(rm1, __shfl_xor_sync(0xffffffffu, rm1, 1));
        rm1 = fmaxf(rm1, __shfl_xor_sync(0xffffffffu, rm1, 2));
        float mn0 = fmaxf(mi0, rm0), mn1 = fmaxf(mi1, rm1);
        float al0 = __expf(mi0 - mn0), al1 = __expf(mi1 - mn1);
        mi0 = mn0;
        mi1 = mn1;
        float rs0 = 0.0f, rs1 = 0.0f;
#pragma unroll
        for (int nt = 0; nt < 8; nt++) {
            S[nt][0] = __expf(S[nt][0] - mn0);
            S[nt][1] = __expf(S[nt][1] - mn0);
            S[nt][2] = __expf(S[nt][2] - mn1);
            S[nt][3] = __expf(S[nt][3] - mn1);
            rs0 += S[nt][0] + S[nt][1];
            rs1 += S[nt][2] + S[nt][3];
        }
        rs0 += __shfl_xor_sync(0xffffffffu, rs0, 1);
        rs0 += __shfl_xor_sync(0xffffffffu, rs0, 2);
        rs1 += __shfl_xor_sync(0xffffffffu, rs1, 1);
        rs1 += __shfl_xor_sync(0xffffffffu, rs1, 2);
        li0 = li0 * al0 + rs0;
        li1 = li1 * al1 + rs1;
#pragma unroll
        for (int nt = 0; nt < 8; nt++) {
            O[nt][0] *= al0;
            O[nt][1] *= al0;
            O[nt][2] *= al1;
            O[nt][3] *= al1;
        }

        // P frags in registers (S C-frag layout == PV A-frag layout)
        uint32_t ph[4][4], pl[4][4];
#pragma unroll
        for (int kt = 0; kt < 4; kt++) {
            bf16 h0, l0, h1, l1;
            split2(S[2 * kt][0], h0, l0);
            split2(S[2 * kt][1], h1, l1);
            ph[kt][0] = pack2bf(h0, h1);
            pl[kt][0] = pack2bf(l0, l1);
            split2(S[2 * kt][2], h0, l0);
            split2(S[2 * kt][3], h1, l1);
            ph[kt][1] = pack2bf(h0, h1);
            pl[kt][1] = pack2bf(l0, l1);
            split2(S[2 * kt + 1][0], h0, l0);
            split2(S[2 * kt + 1][1], h1, l1);
            ph[kt][2] = pack2bf(h0, h1);
            pl[kt][2] = pack2bf(l0, l1);
            split2(S[2 * kt + 1][2], h0, l0);
            split2(S[2 * kt + 1][3], h1, l1);
            ph[kt][3] = pack2bf(h0, h1);
            pl[kt][3] = pack2bf(l0, l1);
        }

        // O += P . V   (V smem is [d][t] k-contiguous)
#pragma unroll
        for (int p = 0; p < 4; p++)
#pragma unroll
            for (int kt = 0; kt < 4; kt++) {
                uint32_t vh[4], vl[4];
                ldm4(vh, mat_addr128(sb + 16384, p * 16, kt * 16, lane));
                ldm4(vl, mat_addr128(sb + 24576, p * 16, kt * 16, lane));
#pragma unroll
                for (int q = 0; q < 2; q++) {
                    int nt = 2 * p + q;
                    mma16816(O[nt], ph[kt], vh[q], vh[2 + q]);
                    mma16816(O[nt], ph[kt], vl[q], vl[2 + q]);
                    mma16816(O[nt], pl[kt], vh[q], vh[2 + q]);
                }
            }

        __syncthreads();  // all warps done reading V_j
        if (j + 1 < nkv) {
            load_tile128<64, 256>(sb + 16384, vhB + kv0 + 64, T_SEQ, tid);
            load_tile128<64, 256>(sb + 24576, vlB + kv0 + 64, T_SEQ, tid);
            cp_commit();
        }
    }

    // finalize: write y (split bf16), y layout [t][h*64+d]
    float inv0 = 1.0f / li0, inv1 = 1.0f / li1;
    int rg0 = qm0 + w * 16 + r0l;
#pragma unroll
    for (int nt = 0; nt < 8; nt++) {
        int d = nt * 8 + c0l;
        size_t i0 = (size_t)rg0 * C_DIM + h * 64 + d;
        size_t i1 = (size_t)(rg0 + 8) * C_DIM + h * 64 + d;
        store_split_pair(g_yhi, g_ylo, i0, O[nt][0] * inv0, O[nt][1] * inv0);
        store_split_pair(g_yhi, g_ylo, i1, O[nt][2] * inv1, O[nt][3] * inv1);
    }
}

// ---------------- launch ----------------
extern "C" void kernel_launch(void* const* d_in, const int* in_sizes, int n_in,
                              void* d_out, int out_size) {
    const float* x = (const float*)d_in[0];
    const float* Wqkv = (const float*)d_in[2];
    const float* bqkv = (const float*)d_in[3];
    const float* Wproj = (const float*)d_in[4];
    const float* bproj = (const float*)d_in[5];
    float* out = (float*)d_out;

    void *xhi, *xlo, *wqhi, *wqlo, *wphi, *wplo, *yhi, *ylo;
    cudaGetSymbolAddress(&xhi, g_xhi);
    cudaGetSymbolAddress(&xlo, g_xlo);
    cudaGetSymbolAddress(&wqhi, g_wqhi);
    cudaGetSymbolAddress(&wqlo, g_wqlo);
    cudaGetSymbolAddress(&wphi, g_wphi);
    cudaGetSymbolAddress(&wplo, g_wplo);
    cudaGetSymbolAddress(&yhi, g_yhi);
    cudaGetSymbolAddress(&ylo, g_ylo);

    conv_x_kernel<<<3072, 256>>>(x);
    transpose_split<<<dim3(72, 24), dim3(32, 8)>>>(Wqkv, (bf16*)wqhi, (bf16*)wqlo, C_DIM, NQKV);
    transpose_split<<<dim3(24, 24), dim3(32, 8)>>>(Wproj, (bf16*)wphi, (bf16*)wplo, C_DIM, C_DIM);
    mma_gemm<0><<<dim3(18, 32), 256>>>((const bf16*)xhi, (const bf16*)xlo, (const bf16*)wqhi,
                                       (const bf16*)wqlo, bqkv, nullptr, NQKV, C_DIM);
    flash_mma<<<dim3(32, H_NUM), 256>>>();
    mma_gemm<1><<<dim3(6, 32), 256>>>((const bf16*)yhi, (const bf16*)ylo, (const bf16*)wphi,
                                      (const bf16*)wplo, bproj, out, C_DIM, C_DIM);
}

// round 16
// speedup vs baseline: 1.0982x; 1.0982x over previous
#include <cuda_runtime.h>
#include <cuda_bf16.h>
#include <cstdint>

typedef __nv_bfloat16 bf16;

#define T_SEQ 4096
#define C_DIM 768
#define H_NUM 12
#define D_DIM 64
#define NQKV  2304

// ---------------- scratch (__device__ globals; no allocation) ----------------
__device__ bf16 g_xhi[T_SEQ * C_DIM], g_xlo[T_SEQ * C_DIM];
__device__ bf16 g_wqhi[NQKV * C_DIM], g_wqlo[NQKV * C_DIM];      // W_qkv^T [N][K]
__device__ bf16 g_wphi[C_DIM * C_DIM], g_wplo[C_DIM * C_DIM];    // W_proj^T [N][K]
__device__ bf16 g_qhi[H_NUM * T_SEQ * D_DIM], g_qlo[H_NUM * T_SEQ * D_DIM];   // [h][t][d], q/8
__device__ bf16 g_khi[H_NUM * T_SEQ * D_DIM], g_klo[H_NUM * T_SEQ * D_DIM];   // [h][t][d]
__device__ bf16 g_vthi[H_NUM * D_DIM * T_SEQ], g_vtlo[H_NUM * D_DIM * T_SEQ]; // [h][d][t]
__device__ bf16 g_yhi[T_SEQ * C_DIM], g_ylo[T_SEQ * C_DIM];

// ---------------- helpers ----------------
__device__ __forceinline__ uint32_t sw128(uint32_t o) { return o ^ ((o >> 3) & 0x70); }
__device__ __forceinline__ uint32_t sw32(uint32_t o) { return o ^ ((o >> 3) & 0x10); }
__device__ __forceinline__ uint32_t smem_u32(const void* p) {
    uint32_t a;
    asm("{ .reg .u64 t; cvta.to.shared.u64 t, %1; cvt.u32.u64 %0, t; }" : "=r"(a) : "l"(p));
    return a;
}
__device__ __forceinline__ void cp16(uint32_t dst, const void* src) {
    asm volatile("cp.async.cg.shared.global [%0], [%1], 16;" :: "r"(dst), "l"(src));
}
__device__ __forceinline__ void cp_commit() { asm volatile("cp.async.commit_group;"); }
template <int N>
__device__ __forceinline__ void cp_wait() {
    asm volatile("cp.async.wait_group %0;" :: "n"(N));
}
__device__ __forceinline__ void ldm4(uint32_t r[4], uint32_t addr) {
    asm volatile("ldmatrix.sync.aligned.m8n8.x4.shared.b16 {%0,%1,%2,%3}, [%4];"
                 : "=r"(r[0]), "=r"(r[1]), "=r"(r[2]), "=r"(r[3]) : "r"(addr));
}
__device__ __forceinline__ void mma16816(float* c, const uint32_t a[4], uint32_t b0,
                                         uint32_t b1) {
    asm volatile("mma.sync.aligned.m16n8k16.row.col.f32.bf16.bf16.f32 "
                 "{%0,%1,%2,%3}, {%4,%5,%6,%7}, {%8,%9}, {%0,%1,%2,%3};"
                 : "+f"(c[0]), "+f"(c[1]), "+f"(c[2]), "+f"(c[3])
                 : "r"(a[0]), "r"(a[1]), "r"(a[2]), "r"(a[3]), "r"(b0), "r"(b1));
}
__device__ __forceinline__ void split2(float v, bf16& h, bf16& l) {
    h = __float2bfloat16(v);
    l = __float2bfloat16(v - __bfloat162float(h));
}
__device__ __forceinline__ uint32_t pack2bf(bf16 a, bf16 b) {
    return (uint32_t)__bfloat16_as_ushort(a) | ((uint32_t)__bfloat16_as_ushort(b) << 16);
}
__device__ __forceinline__ void store_split_pair(bf16* hiA, bf16* loA, size_t idx, float v0,
                                                 float v1) {
    bf16 h0, l0, h1, l1;
    split2(v0, h0, l0);
    split2(v1, h1, l1);
    *(uint32_t*)(hiA + idx) = pack2bf(h0, h1);
    *(uint32_t*)(loA + idx) = pack2bf(l0, l1);
}

// ldmatrix x4 address in a [rows][64 halves] tile, 128B rows, SW128
__device__ __forceinline__ uint32_t mat_addr128(uint32_t base, int rbase, int kbase, int lane) {
    int row = rbase + (lane & 15);
    uint32_t off = row * 128 + kbase * 2 + ((lane >> 4) << 4);
    return base + sw128(off);
}
// ldmatrix x4 address in a [rows][16 halves] tile, 32B rows, sw32
__device__ __forceinline__ uint32_t mat_addr32(uint32_t base, int rbase, int lane) {
    int row = rbase + (lane & 15);
    uint32_t off = row * 32 + ((lane >> 4) << 4);
    return base + sw32(off);
}

// async tile loads
template <int ROWS, int NT>
__device__ __forceinline__ void load_tile128(uint32_t dst, const bf16* __restrict__ src,
                                             int ldK, int tid) {
#pragma unroll
    for (int i = 0; i < ROWS * 8 / NT; i++) {
        int ch = tid + i * NT;
        int row = ch >> 3, ci = ch & 7;
        cp16(dst + sw128(row * 128 + ci * 16), src + (size_t)row * ldK + ci * 8);
    }
}
template <int ROWS, int NT>
__device__ __forceinline__ void load_tile32(uint32_t dst, const bf16* __restrict__ src,
                                            int ldK, int tid) {
#pragma unroll
    for (int i = 0; i < ROWS * 2 / NT; i++) {
        int ch = tid + i * NT;
        int row = ch >> 1, ci = ch & 1;
        cp16(dst + sw32(row * 32 + ci * 16), src + (size_t)row * ldK + ci * 8);
    }
}

// ---------------- converters ----------------
__global__ void conv_x_kernel(const float* __restrict__ x) {
    int i = (blockIdx.x * blockDim.x + threadIdx.x) * 4;
    float4 v = *(const float4*)(x + i);
    float e[4] = {v.x, v.y, v.z, v.w};
#pragma unroll
    for (int j = 0; j < 4; j++) {
        bf16 h, l;
        split2(e[j], h, l);
        g_xhi[i + j] = h;
        g_xlo[i + j] = l;
    }
}
__global__ void transpose_split(const float* __restrict__ W, bf16* __restrict__ hi,
                                bf16* __restrict__ lo, int K, int N) {
    __shared__ float t[32][33];
    int n0 = blockIdx.x * 32, k0 = blockIdx.y * 32;
    int tx = threadIdx.x, ty = threadIdx.y;
#pragma unroll
    for (int i = 0; i < 4; i++) t[ty + i * 8][tx] = W[(size_t)(k0 + ty + i * 8) * N + n0 + tx];
    __syncthreads();
#pragma unroll
    for (int i = 0; i < 4; i++) {
        int n = n0 + ty + i * 8;
        bf16 h, l;
        split2(t[tx][ty + i * 8], h, l);
        hi[(size_t)n * K + k0 + tx] = h;
        lo[(size_t)n * K + k0 + tx] = l;
    }
}

// ---------------- HMMA GEMM: D[128x128] = A[128xK] . B^T, B stored [N][K] ----------
// 3-stage cp.async ring, ONE barrier per stage: wait -> sync -> issue(s+2) -> compute(s).
template <int MODE>
__global__ __launch_bounds__(256) void mma_gemm(const bf16* __restrict__ Ahi,
                                                const bf16* __restrict__ Alo,
                                                const bf16* __restrict__ Bhi,
                                                const bf16* __restrict__ Blo,
                                                const float* __restrict__ bias,
                                                float* __restrict__ Cout, int N, int K) {
    __shared__ char smem[49152];
    uint32_t sb = smem_u32(smem);
    const int tid = threadIdx.x, lane = tid & 31, warp = tid >> 5;
    const int wm = warp >> 2, wn = warp & 3;  // 2 x 4 warp grid, 64m x 32n per warp
    const int m0 = blockIdx.y * 128, n0 = blockIdx.x * 128;

    const bf16* Ah = Ahi + (size_t)m0 * K;
    const bf16* Al = Alo + (size_t)m0 * K;
    const bf16* Bh = Bhi + (size_t)n0 * K;
    const bf16* Bl = Blo + (size_t)n0 * K;

    float acc[4][4][4];
#pragma unroll
    for (int mt = 0; mt < 4; mt++)
#pragma unroll
        for (int nt = 0; nt < 4; nt++)
#pragma unroll
            for (int e = 0; e < 4; e++) acc[mt][nt][e] = 0.0f;

    const int NS = K / 16;
    // prefetch stages 0,1
#pragma unroll
    for (int p = 0; p < 2; p++) {
        uint32_t b = sb + p * 16384;
        int k0 = p * 16;
        load_tile32<128, 256>(b, Ah + k0, K, tid);
        load_tile32<128, 256>(b + 4096, Al + k0, K, tid);
        load_tile32<128, 256>(b + 8192, Bh + k0, K, tid);
        load_tile32<128, 256>(b + 12288, Bl + k0, K, tid);
        cp_commit();
    }
#pragma unroll 1
    for (int s = 0; s < NS; s++) {
        if (s + 1 < NS) cp_wait<1>();
        else cp_wait<0>();
        __syncthreads();   // stage s readable; all threads past stage s-1 compute
        if (s + 2 < NS) {  // safe: buffer (s+2)%3 == (s-1)%3, reads finished above
            uint32_t b = sb + ((s + 2) % 3) * 16384;
            int k0 = (s + 2) * 16;
            load_tile32<128, 256>(b, Ah + k0, K, tid);
            load_tile32<128, 256>(b + 4096, Al + k0, K, tid);
            load_tile32<128, 256>(b + 8192, Bh + k0, K, tid);
            load_tile32<128, 256>(b + 12288, Bl + k0, K, tid);
            cp_commit();
        }
        uint32_t b = sb + (s % 3) * 16384;
        uint32_t ah[4][4], al[4][4];
#pragma unroll
        for (int mt = 0; mt < 4; mt++) {
            ldm4(ah[mt], mat_addr32(b, wm * 64 + mt * 16, lane));
            ldm4(al[mt], mat_addr32(b + 4096, wm * 64 + mt * 16, lane));
        }
#pragma unroll
        for (int p = 0; p < 2; p++) {
            uint32_t bh[4], bl[4];
            ldm4(bh, mat_addr32(b + 8192, wn * 32 + p * 16, lane));
            ldm4(bl, mat_addr32(b + 12288, wn * 32 + p * 16, lane));
#pragma unroll
            for (int mt = 0; mt < 4; mt++)
#pragma unroll
                for (int q = 0; q < 2; q++) {
                    int nt = p * 2 + q;
                    mma16816(acc[mt][nt], ah[mt], bh[q], bh[2 + q]);
                    mma16816(acc[mt][nt], ah[mt], bl[q], bl[2 + q]);
                    mma16816(acc[mt][nt], al[mt], bh[q], bh[2 + q]);
                }
        }
    }

    // epilogue: acc[mt][nt]: rows r0,r0+8 ; cols c0,c0+1
#pragma unroll
    for (int mt = 0; mt < 4; mt++)
#pragma unroll
        for (int nt = 0; nt < 4; nt++) {
            int r0 = m0 + wm * 64 + mt * 16 + (lane >> 2);
            int c0 = n0 + wn * 32 + nt * 8 + 2 * (lane & 3);
            float bv0 = bias[c0], bv1 = bias[c0 + 1];
            float v0 = acc[mt][nt][0] + bv0, v1 = acc[mt][nt][1] + bv1;
            float v2 = acc[mt][nt][2] + bv0, v3 = acc[mt][nt][3] + bv1;
            if (MODE == 1) {
                float2 p0 = make_float2(v0, v1), p1 = make_float2(v2, v3);
                *(float2*)&Cout[(size_t)r0 * N + c0] = p0;
                *(float2*)&Cout[(size_t)(r0 + 8) * N + c0] = p1;
            } else {
                int which = n0 / C_DIM;
                int cm = c0 % C_DIM;
                int h = cm >> 6, d = cm & 63;
                if (which == 0) {
                    store_split_pair(g_qhi, g_qlo, ((size_t)h * T_SEQ + r0) * D_DIM + d,
                                     v0 * 0.125f, v1 * 0.125f);
                    store_split_pair(g_qhi, g_qlo, ((size_t)h * T_SEQ + r0 + 8) * D_DIM + d,
                                     v2 * 0.125f, v3 * 0.125f);
                } else if (which == 1) {
                    store_split_pair(g_khi, g_klo, ((size_t)h * T_SEQ + r0) * D_DIM + d, v0, v1);
                    store_split_pair(g_khi, g_klo, ((size_t)h * T_SEQ + r0 + 8) * D_DIM + d, v2,
                                     v3);
                } else {
                    size_t b0 = ((size_t)h * D_DIM + d) * T_SEQ;
                    size_t b1 = ((size_t)h * D_DIM + d + 1) * T_SEQ;
                    bf16 hh, ll;
                    split2(v0, hh, ll); g_vthi[b0 + r0] = hh; g_vtlo[b0 + r0] = ll;
                    split2(v1, hh, ll); g_vthi[b1 + r0] = hh; g_vtlo[b1 + r0] = ll;
                    split2(v2, hh, ll); g_vthi[b0 + r0 + 8] = hh; g_vtlo[b0 + r0 + 8] = ll;
                    split2(v3, hh, ll); g_vthi[b1 + r0 + 8] = hh; g_vtlo[b1 + r0 + 8] = ll;
                }
            }
        }
}

// ---------------- flash attention on HMMA (R10 shape: 64-row q-tiles, 4 warps) --------
// Block: 128 threads, 64 q-rows (warp w owns rows w*16..+15), kv tiles of 64.
// 2-pass pairing qb <-> 63-qb for exact load balance (66 kv-iters per block).
// smem: Khi 8K | Klo 8K | Vhi 8K | Vlo 8K (K area doubles as Q staging).
// Staggered prefetch: V_j load overlaps S_j; K_{j+1} issue overlaps softmax+PV_j;
//                     V_{j+1} issue after the V-read barrier.
__global__ __launch_bounds__(128) void flash_mma() {
    __shared__ char smem[32768];
    uint32_t sb = smem_u32(smem);
    const int tid = threadIdx.x, lane = tid & 31, w = tid >> 5;
    const int h = blockIdx.y;
    const int r0l = lane >> 2;
    const int c0l = 2 * (lane & 3);

    const bf16* khB = g_khi + (size_t)h * T_SEQ * D_DIM;
    const bf16* klB = g_klo + (size_t)h * T_SEQ * D_DIM;
    const bf16* vhB = g_vthi + (size_t)h * D_DIM * T_SEQ;
    const bf16* vlB = g_vtlo + (size_t)h * D_DIM * T_SEQ;

#pragma unroll 1
    for (int pass = 0; pass < 2; pass++) {
        const int qb = pass ? 63 - (int)blockIdx.x : (int)blockIdx.x;
        const int qm0 = qb * 64;

        __syncthreads();
        load_tile128<64, 128>(sb, g_qhi + ((size_t)h * T_SEQ + qm0) * D_DIM, D_DIM, tid);
        load_tile128<64, 128>(sb + 8192, g_qlo + ((size_t)h * T_SEQ + qm0) * D_DIM, D_DIM, tid);
        cp_commit();
        cp_wait<0>();
        __syncthreads();

        uint32_t qh[4][4], ql[4][4];
#pragma unroll
        for (int kt = 0; kt < 4; kt++) {
            ldm4(qh[kt], mat_addr128(sb, w * 16, kt * 16, lane));
            ldm4(ql[kt], mat_addr128(sb + 8192, w * 16, kt * 16, lane));
        }
        __syncthreads();  // all warps done reading Q staging before K0 overwrites

        // issue K0 then V0 as separate groups
        load_tile128<64, 128>(sb, khB, D_DIM, tid);
        load_tile128<64, 128>(sb + 8192, klB, D_DIM, tid);
        cp_commit();
        load_tile128<64, 128>(sb + 16384, vhB, T_SEQ, tid);
        load_tile128<64, 128>(sb + 24576, vlB, T_SEQ, tid);
        cp_commit();

        float mi0 = -1e30f, mi1 = -1e30f, li0 = 0.0f, li1 = 0.0f;
        float O[8][4];
#pragma unroll
        for (int nt = 0; nt < 8; nt++)
#pragma unroll
            for (int e = 0; e < 4; e++) O[nt][e] = 0.0f;

        const int nkv = qb + 1;
#pragma unroll 1
        for (int j = 0; j < nkv; j++) {
            const int kv0 = j * 64;
            cp_wait<1>();  // K_j complete (V_j may still be in flight)
            __syncthreads();

            // S = Q . K^T
            float S[8][4];
#pragma unroll
            for (int nt = 0; nt < 8; nt++)
#pragma unroll
                for (int e = 0; e < 4; e++) S[nt][e] = 0.0f;
#pragma unroll
            for (int p = 0; p < 4; p++)
#pragma unroll
                for (int kt = 0; kt < 4; kt++) {
                    uint32_t kh[4], kl[4];
                    ldm4(kh, mat_addr128(sb, p * 16, kt * 16, lane));
                    ldm4(kl, mat_addr128(sb + 8192, p * 16, kt * 16, lane));
#pragma unroll
                    for (int q = 0; q < 2; q++) {
                        int nt = 2 * p + q;
                        mma16816(S[nt], qh[kt], kh[q], kh[2 + q]);
                        mma16816(S[nt], qh[kt], kl[q], kl[2 + q]);
                        mma16816(S[nt], ql[kt], kh[q], kh[2 + q]);
                    }
                }

            cp_wait<0>();     // V_j complete
            __syncthreads();  // all warps done reading K_j

            // prefetch K_{j+1} over softmax + PV compute
            if (j + 1 < nkv) {
                load_tile128<64, 128>(sb, khB + (size_t)(kv0 + 64) * D_DIM, D_DIM, tid);
                load_tile128<64, 128>(sb + 8192, klB + (size_t)(kv0 + 64) * D_DIM, D_DIM, tid);
                cp_commit();
            }

            if (j == qb) {  // diagonal: causal mask
                int rg0 = qm0 + w * 16 + r0l, rg1 = rg0 + 8;
#pragma unroll
                for (int nt = 0; nt < 8; nt++) {
                    int cg = kv0 + nt * 8 + c0l;
                    if (cg > rg0) S[nt][0] = -1e30f;
                    if (cg + 1 > rg0) S[nt][1] = -1e30f;
                    if (cg > rg1) S[nt][2] = -1e30f;
                    if (cg + 1 > rg1) S[nt][3] = -1e30f;
                }
            }

            // online softmax (rows r0l, r0l+8; reduce over lanes xor 1,2)
            float rm0 = -1e30f, rm1 = -1e30f;
#pragma unroll
            for (int nt = 0; nt < 8; nt++) {
                rm0 = fmaxf(rm0, fmaxf(S[nt][0], S[nt][1]));
                rm1 = fmaxf(rm1, fmaxf(S[nt][2], S[nt][3]));
            }
            rm0 = fmaxf(rm0, __shfl_xor_sync(0xffffffffu, rm0, 1));
            rm0 = fmaxf(rm0, __shfl_xor_sync(0xffffffffu, rm0, 2));
            rm1 = fmaxf(rm1, __shfl_xor_sync(0xffffffffu, rm1, 1));
            rm1 = fmaxf(rm1, __shfl_xor_sync(0xffffffffu, rm1, 2));
            float mn0 = fmaxf(mi0, rm0), mn1 = fmaxf(mi1, rm1);
            float al0 = __expf(mi0 - mn0), al1 = __expf(mi1 - mn1);
            mi0 = mn0;
            mi1 = mn1;
            float rs0 = 0.0f, rs1 = 0.0f;
#pragma unroll
            for (int nt = 0; nt < 8; nt++) {
                S[nt][0] = __expf(S[nt][0] - mn0);
                S[nt][1] = __expf(S[nt][1] - mn0);
                S[nt][2] = __expf(S[nt][2] - mn1);
                S[nt][3] = __expf(S[nt][3] - mn1);
                rs0 += S[nt][0] + S[nt][1];
                rs1 += S[nt][2] + S[nt][3];
            }
            rs0 += __shfl_xor_sync(0xffffffffu, rs0, 1);
            rs0 += __shfl_xor_sync(0xffffffffu, rs0, 2);
            rs1 += __shfl_xor_sync(0xffffffffu, rs1, 1);
            rs1 += __shfl_xor_sync(0xffffffffu, rs1, 2);
            li0 = li0 * al0 + rs0;
            li1 = li1 * al1 + rs1;
#pragma unroll
            for (int nt = 0; nt < 8; nt++) {
                O[nt][0] *= al0;
                O[nt][1] *= al0;
                O[nt][2] *= al1;
                O[nt][3] *= al1;
            }

            // P frags in registers (S C-frag layout == PV A-frag layout)
            uint32_t ph[4][4], pl[4][4];
#pragma unroll
            for (int kt = 0; kt < 4; kt++) {
                bf16 h0, l0, h1, l1;
                split2(S[2 * kt][0], h0, l0);
                split2(S[2 * kt][1], h1, l1);
                ph[kt][0] = pack2bf(h0, h1);
                pl[kt][0] = pack2bf(l0, l1);
                split2(S[2 * kt][2], h0, l0);
                split2(S[2 * kt][3], h1, l1);
                ph[kt][1] = pack2bf(h0, h1);
                pl[kt][1] = pack2bf(l0, l1);
                split2(S[2 * kt + 1][0], h0, l0);
                split2(S[2 * kt + 1][1], h1, l1);
                ph[kt][2] = pack2bf(h0, h1);
                pl[kt][2] = pack2bf(l0, l1);
                split2(S[2 * kt + 1][2], h0, l0);
                split2(S[2 * kt + 1][3], h1, l1);
                ph[kt][3] = pack2bf(h0, h1);
                pl[kt][3] = pack2bf(l0, l1);
            }

            // O += P . V   (V smem is [d][t] k-contiguous)
#pragma unroll
            for (int p = 0; p < 4; p++)
#pragma unroll
                for (int kt = 0; kt < 4; kt++) {
                    uint32_t vh[4], vl[4];
                    ldm4(vh, mat_addr128(sb + 16384, p * 16, kt * 16, lane));
                    ldm4(vl, mat_addr128(sb + 24576, p * 16, kt * 16, lane));
#pragma unroll
                    for (int q = 0; q < 2; q++) {
                        int nt = 2 * p + q;
                        mma16816(O[nt], ph[kt], vh[q], vh[2 + q]);
                        mma16816(O[nt], ph[kt], vl[q], vl[2 + q]);
                        mma16816(O[nt], pl[kt], vh[q], vh[2 + q]);
                    }
                }

            __syncthreads();  // all warps done reading V_j
            if (j + 1 < nkv) {
                load_tile128<64, 128>(sb + 16384, vhB + kv0 + 64, T_SEQ, tid);
                load_tile128<64, 128>(sb + 24576, vlB + kv0 + 64, T_SEQ, tid);
                cp_commit();
            }
        }

        // finalize: write y (split bf16), y layout [t][h*64+d]
        float inv0 = 1.0f / li0, inv1 = 1.0f / li1;
        int rg0 = qm0 + w * 16 + r0l;
#pragma unroll
        for (int nt = 0; nt < 8; nt++) {
            int d = nt * 8 + c0l;
            size_t i0 = (size_t)rg0 * C_DIM + h * 64 + d;
            size_t i1 = (size_t)(rg0 + 8) * C_DIM + h * 64 + d;
            store_split_pair(g_yhi, g_ylo, i0, O[nt][0] * inv0, O[nt][1] * inv0);
            store_split_pair(g_yhi, g_ylo, i1, O[nt][2] * inv1, O[nt][3] * inv1);
        }
    }
}

// ---------------- launch ----------------
extern "C" void kernel_launch(void* const* d_in, const int* in_sizes, int n_in,
                              void* d_out, int out_size) {
    const float* x = (const float*)d_in[0];
    const float* Wqkv = (const float*)d_in[2];
    const float* bqkv = (const float*)d_in[3];
    const float* Wproj = (const float*)d_in[4];
    const float* bproj = (const float*)d_in[5];
    float* out = (float*)d_out;

    void *xhi, *xlo, *wqhi, *wqlo, *wphi, *wplo, *yhi, *ylo;
    cudaGetSymbolAddress(&xhi, g_xhi);
    cudaGetSymbolAddress(&xlo, g_xlo);
    cudaGetSymbolAddress(&wqhi, g_wqhi);
    cudaGetSymbolAddress(&wqlo, g_wqlo);
    cudaGetSymbolAddress(&wphi, g_wphi);
    cudaGetSymbolAddress(&wplo, g_wplo);
    cudaGetSymbolAddress(&yhi, g_yhi);
    cudaGetSymbolAddress(&ylo, g_ylo);

    conv_x_kernel<<<3072, 256>>>(x);
    transpose_split<<<dim3(72, 24), dim3(32, 8)>>>(Wqkv, (bf16*)wqhi, (bf16*)wqlo, C_DIM, NQKV);
    transpose_split<<<dim3(24, 24), dim3(32, 8)>>>(Wproj, (bf16*)wphi, (bf16*)wplo, C_DIM, C_DIM);
    mma_gemm<0><<<dim3(18, 32), 256>>>((const bf16*)xhi, (const bf16*)xlo, (const bf16*)wqhi,
                                       (const bf16*)wqlo, bqkv, nullptr, NQKV, C_DIM);
    flash_mma<<<dim3(32, H_NUM), 128>>>();
    mma_gemm<1><<<dim3(6, 32), 256>>>((const bf16*)yhi, (const bf16*)ylo, (const bf16*)wphi,
                                      (const bf16*)wplo, bproj, out, C_DIM, C_DIM);
}